// round 1
// baseline (speedup 1.0000x reference)
#include <cuda_runtime.h>
#include <math.h>

// ElasticBand (NEB) — everything nonlinear reduces to per-image scalars.
// Pass A: 6 base reductions per interior image (rolling window: pos read once).
// Pass B: fold partials + eng logic -> (g1, alpha, beta) per interior image.
// Pass C: out = g1*frc + alpha*(pos[i]-pos[i-1]) + beta*(pos[i+1]-pos[i]).

#define KMAXC 0.1f
#define DLTKC 0.02f
#define EPSC  0.1f

#define TA   256      // threads, kernel A
#define KPT  2        // float4 per thread per image, kernel A
#define MAX_INT 62    // max interior images supported
#define MAX_NB  1280  // max partial blocks supported

// [interior][block][6] partials, packed densely at runtime stride nb*6
__device__ float g_part[(size_t)MAX_INT * MAX_NB * 6];
// per interior image: g1, alpha, beta, pad
__device__ float g_coef[MAX_INT * 4];

__device__ __forceinline__ float warpSum(float v) {
    #pragma unroll
    for (int o = 16; o > 0; o >>= 1) v += __shfl_xor_sync(0xffffffffu, v, o);
    return v;
}

// -------- Kernel A: rolling per-image reductions ---------------------------
__global__ void __launch_bounds__(TA) nebReduce(
    const float4* __restrict__ pos4,
    const float4* __restrict__ frc4,
    int nvec, int n_img, int nb)
{
    const int b = blockIdx.x;
    const int t = threadIdx.x;

    int   idx[KPT];
    bool  ok[KPT];
    float4 pPrev[KPT], pCur[KPT];

    #pragma unroll
    for (int k = 0; k < KPT; k++) {
        int j = b * (TA * KPT) + k * TA + t;
        idx[k] = j;
        ok[k]  = (j < nvec);
        if (ok[k]) {
            pPrev[k] = pos4[j];                     // image 0
            pCur[k]  = pos4[(size_t)nvec + j];      // image 1
        } else {
            pPrev[k] = make_float4(0.f, 0.f, 0.f, 0.f);
            pCur[k]  = make_float4(0.f, 0.f, 0.f, 0.f);
        }
    }

    __shared__ float sred[6][TA / 32];
    const int n_int = n_img - 2;

    for (int ii = 0; ii < n_int; ii++) {
        const int i = ii + 1;   // global interior image
        float vA = 0.f, vB = 0.f, vC = 0.f, vD = 0.f, vE = 0.f, vW = 0.f;

        #pragma unroll
        for (int k = 0; k < KPT; k++) {
            if (ok[k]) {
                float4 pN = pos4[(size_t)(i + 1) * nvec + idx[k]];
                float4 f  = frc4[(size_t)i * nvec + idx[k]];

                float dpx = pCur[k].x - pPrev[k].x, dmx = pN.x - pCur[k].x;
                float dpy = pCur[k].y - pPrev[k].y, dmy = pN.y - pCur[k].y;
                float dpz = pCur[k].z - pPrev[k].z, dmz = pN.z - pCur[k].z;
                float dpw = pCur[k].w - pPrev[k].w, dmw = pN.w - pCur[k].w;

                vA = fmaf(dpx, dpx, fmaf(dpy, dpy, fmaf(dpz, dpz, fmaf(dpw, dpw, vA))));
                vB = fmaf(dmx, dmx, fmaf(dmy, dmy, fmaf(dmz, dmz, fmaf(dmw, dmw, vB))));
                vC = fmaf(dpx, dmx, fmaf(dpy, dmy, fmaf(dpz, dmz, fmaf(dpw, dmw, vC))));
                vD = fmaf(f.x, dpx, fmaf(f.y, dpy, fmaf(f.z, dpz, fmaf(f.w, dpw, vD))));
                vE = fmaf(f.x, dmx, fmaf(f.y, dmy, fmaf(f.z, dmz, fmaf(f.w, dmw, vE))));
                vW = fmaf(f.x, f.x, fmaf(f.y, f.y, fmaf(f.z, f.z, fmaf(f.w, f.w, vW))));

                pPrev[k] = pCur[k];
                pCur[k]  = pN;
            }
        }

        float vals[6] = { vA, vB, vC, vD, vE, vW };
        #pragma unroll
        for (int c = 0; c < 6; c++) {
            float r = warpSum(vals[c]);
            if ((t & 31) == 0) sred[c][t >> 5] = r;
        }
        __syncthreads();
        if (t < 6) {
            float s = 0.f;
            #pragma unroll
            for (int w = 0; w < TA / 32; w++) s += sred[t][w];
            g_part[((size_t)ii * nb + b) * 6 + t] = s;
        }
        __syncthreads();
    }
}

// -------- Kernel B: fold partials + eng scalars -> coefficients ------------
__device__ __forceinline__ float spring_k(float ea, float eb, float emax, float eref) {
    float ei = fmaxf(ea, eb);
    float k = KMAXC - DLTKC * (emax - ei) / (emax - eref);
    if (ei < eref) k = KMAXC - DLTKC;
    return k;
}

__global__ void nebScalars(const float* __restrict__ eng, int n_img, int nb)
{
    const int j = blockIdx.x;    // interior index 0..n_int-1
    const int t = threadIdx.x;   // 256

    float acc[6] = {0.f, 0.f, 0.f, 0.f, 0.f, 0.f};
    for (int b = t; b < nb; b += blockDim.x) {
        #pragma unroll
        for (int c = 0; c < 6; c++)
            acc[c] += g_part[((size_t)j * nb + b) * 6 + c];
    }

    __shared__ float sred[6][8];
    #pragma unroll
    for (int c = 0; c < 6; c++) {
        float r = warpSum(acc[c]);
        if ((t & 31) == 0) sred[c][t >> 5] = r;
    }
    __syncthreads();

    if (t == 0) {
        float S[6];
        #pragma unroll
        for (int c = 0; c < 6; c++) {
            float s = 0.f;
            #pragma unroll
            for (int w = 0; w < 8; w++) s += sred[c][w];
            S[c] = s;
        }
        const float A = S[0], B = S[1], C = S[2], D = S[3], E = S[4], W = S[5];

        // eng-derived scalars
        float emin = eng[0], emax = eng[0];
        int   imax = 0;
        for (int p = 1; p < n_img; p++) {
            float e = eng[p];
            if (e < emin) emin = e;
            if (e > emax) { emax = e; imax = p; }   // strict > keeps first max (jnp.argmax)
        }
        const float eref = emin - EPSC;

        const int i = j + 1;
        const float e0 = eng[i - 1], e1 = eng[i], e2 = eng[i + 1];
        const float km = spring_k(e0, e1, emax, eref);  // k[:-1][j]
        const float kp = spring_k(e1, e2, emax, eref);  // k[1:][j]

        float cp, cm;
        if (e2 > e1 && e1 > e0)      { cp = 1.f;  cm = 0.f; }
        else if (e2 < e1 && e1 < e0) { cp = 0.f;  cm = 1.f; }
        else {
            float d1 = fabsf(e2 - e1), d0 = fabsf(e0 - e1);
            float dvmax = fmaxf(d1, d0), dvmin = fminf(d1, d0);
            if (e2 > e1)      { cp = dvmax; cm = dvmin; }
            else if (e2 < e1) { cp = dvmin; cm = dvmax; }
            else              { cp = 0.f;   cm = 0.f; }
        }

        const float Stt = cp * cp * A + 2.f * cp * cm * C + cm * cm * B;
        const float Sft = cp * D + cm * E;
        const float a   = Sft / Stt;
        const float s   = (kp * sqrtf(B) - km * sqrtf(A)) / sqrtf(Stt);

        const float F   = W - Sft * Sft / Stt;                  // ||frc_perp||^2
        const float Tm  = cp * C + cm * B;                      // tau_m . tau_raw
        const float Tp  = cp * A + cm * C;                      // tau_p . tau_raw
        const float St  = kp * Tm - km * Tp;                    // spr . tau_raw
        const float G   = kp * kp * B + km * km * A - 2.f * kp * km * C
                          - 2.f * s * St + s * s * Stt;         // ||spr_perp||^2
        const float Sf  = kp * E - km * D;                      // spr . frc
        const float H   = Sf - a * St - s * Sft + s * a * Stt;  // spr_perp . frc_perp

        const float sw  = (2.0f / 3.14159265358979323846f) * atan2f(F, G);
        const float Hsw = H * sw;
        const float mult = (j == imax) ? 2.f : 1.f;             // .at[i_raw]; OOB -> no-op

        g_coef[j * 4 + 0] = 1.f - Hsw;
        g_coef[j * 4 + 1] = a * (Hsw - mult) * cp - km;         // coeff of dp
        g_coef[j * 4 + 2] = a * (Hsw - mult) * cm + kp;         // coeff of dm
    }
}

// -------- Kernel C: streaming output ---------------------------------------
__global__ void nebOut(
    const float4* __restrict__ pos4,
    const float4* __restrict__ frc4,
    float4* __restrict__ out4,
    int nvec, int n_img)
{
    size_t gid = (size_t)blockIdx.x * blockDim.x + threadIdx.x;
    size_t total = (size_t)n_img * nvec;
    if (gid >= total) return;

    int img = (int)(gid / (unsigned)nvec);
    float4 f = frc4[gid];

    if (img == 0 || img == n_img - 1) { out4[gid] = f; return; }

    const int ii = img - 1;
    const float g1 = __ldg(&g_coef[ii * 4 + 0]);
    const float al = __ldg(&g_coef[ii * 4 + 1]);
    const float be = __ldg(&g_coef[ii * 4 + 2]);

    float4 pm = pos4[gid - nvec];
    float4 pc = pos4[gid];
    float4 pp = pos4[gid + nvec];

    float4 o;
    o.x = fmaf(g1, f.x, fmaf(al, pc.x - pm.x, be * (pp.x - pc.x)));
    o.y = fmaf(g1, f.y, fmaf(al, pc.y - pm.y, be * (pp.y - pc.y)));
    o.z = fmaf(g1, f.z, fmaf(al, pc.z - pm.z, be * (pp.z - pc.z)));
    o.w = fmaf(g1, f.w, fmaf(al, pc.w - pm.w, be * (pp.w - pc.w)));
    out4[gid] = o;
}

// ---------------------------------------------------------------------------
extern "C" void kernel_launch(void* const* d_in, const int* in_sizes, int n_in,
                              void* d_out, int out_size)
{
    const float* pos = (const float*)d_in[0];
    const float* frc = (const float*)d_in[1];
    const float* eng = (const float*)d_in[2];

    const int n_img     = in_sizes[2];                 // 32
    const long per_img  = (long)in_sizes[0] / n_img;   // 1,200,000 floats
    const int  nvec     = (int)(per_img / 4);          // 300,000 float4 (divisible)
    const int  n_int    = n_img - 2;

    const int nb = (nvec + TA * KPT - 1) / (TA * KPT); // partial blocks per image

    const float4* pos4 = (const float4*)pos;
    const float4* frc4 = (const float4*)frc;
    float4* out4 = (float4*)d_out;

    nebReduce<<<nb, TA>>>(pos4, frc4, nvec, n_img, nb);
    nebScalars<<<n_int, 256>>>(eng, n_img, nb);

    size_t total = (size_t)n_img * nvec;
    int blocksC = (int)((total + 255) / 256);
    nebOut<<<blocksC, 256>>>(pos4, frc4, out4, nvec, n_img);
}